// round 6
// baseline (speedup 1.0000x reference)
#include <cuda_runtime.h>
#include <math.h>

// Problem constants
#define B_ 512
#define T_ 2048
#define H_ 128
#define E_ 256
#define V_ 34

// Output layout: (out[B,V], c[B,H], sh0[B,H], sh1[B,H], sc0[B,H], sc1[B,H], atten_vec[T])
#define OFF_OUT 0
#define OFF_C   (B_*V_)
#define OFF_SH0 (OFF_C   + B_*H_)
#define OFF_SH1 (OFF_SH0 + B_*H_)
#define OFF_SC0 (OFF_SH1 + B_*H_)
#define OFF_SC1 (OFF_SC0 + B_*H_)
#define OFF_ATT (OFF_SC1 + B_*H_)

// Scratch (__device__ globals; no allocations allowed)
__device__ float g_pre[B_*H_];   // head pre-BN output
__device__ float g_mean[H_];
__device__ float g_var[H_];

__device__ __forceinline__ float sigm(float x) { return 1.f / (1.f + __expf(-x)); }

// ---------------------------------------------------------------------------
// Fused LSTM cell: gates = [Xseg0|Xseg1|Xseg2] @ [W_ih|W_hh]^T + b_ih + b_hh,
// then i/f/g/o activations -> h_out, c_out.  No concat materialization.
//
// Tile: 16 rows (batch) x 16 h (= 64 gate-cols, col = h_local*4 + gate).
// Grid (H/16=8, B/16=32) = 256 blocks, 256 threads, double-buffered smem.
// Thread (tx 0..15, ty 0..15): row m0+ty; h = h0+tx; 4 gates.
// ---------------------------------------------------------------------------
__global__ void __launch_bounds__(256) k_lstm(
    const float* __restrict__ A, int ka,
    const float* __restrict__ Bp, int kb,
    const float* __restrict__ Cp, int kc,
    const float* __restrict__ Wih, int Kin,
    const float* __restrict__ Whh,
    const float* __restrict__ bih, const float* __restrict__ bhh,
    const float* __restrict__ c_prev,
    float* __restrict__ h_out, float* __restrict__ c_out)
{
    __shared__ float Xs[2][16][17];
    __shared__ float Ws[2][16][68];
    const int tid = threadIdx.x;
    const int tx = tid & 15, ty = tid >> 4;
    const int m0 = blockIdx.y * 16;
    const int h0 = blockIdx.x * 16;
    const int lkk = tid & 15, lr = tid >> 4;
    const int K = ka + kb + kc;
    const int nt = K >> 4;

    // W row index for each of this thread's 4 loader columns (col = lr + p*16)
    int wn[4];
    #pragma unroll
    for (int p = 0; p < 4; p++) {
        int c = lr + p * 16;
        wn[p] = (c & 3) * H_ + h0 + (c >> 2);   // gate*H + h
    }

    // prologue: tile 0 -> smem buf 0
    {
        int k = lkk;
        float x0;
        if (k < ka)            x0 = A[(m0+lr)*ka + k];
        else if (k < ka + kb)  x0 = Bp[(m0+lr)*kb + k - ka];
        else                   x0 = Cp[(m0+lr)*kc + k - ka - kb];
        Xs[0][lkk][lr] = x0;
        #pragma unroll
        for (int p = 0; p < 4; p++)
            Ws[0][lkk][lr + p*16] = (k < Kin) ? Wih[wn[p]*Kin + k] : Whh[wn[p]*H_ + k - Kin];
    }
    __syncthreads();

    float acc[4] = {};
    for (int it = 0; it < nt; it++) {
        const int cur = it & 1, nxt = cur ^ 1;
        float px0 = 0.f, pw[4] = {0.f,0.f,0.f,0.f};
        const bool more = (it + 1 < nt);
        if (more) {
            int k = (it + 1) * 16 + lkk;
            if (k < ka)            px0 = A[(m0+lr)*ka + k];
            else if (k < ka + kb)  px0 = Bp[(m0+lr)*kb + k - ka];
            else                   px0 = Cp[(m0+lr)*kc + k - ka - kb];
            #pragma unroll
            for (int p = 0; p < 4; p++)
                pw[p] = (k < Kin) ? Wih[wn[p]*Kin + k] : Whh[wn[p]*H_ + k - Kin];
        }
        #pragma unroll
        for (int kk = 0; kk < 16; kk++) {
            float x0 = Xs[cur][kk][ty];
            float4 wv = *(const float4*)&Ws[cur][kk][tx*4];
            acc[0] = fmaf(x0, wv.x, acc[0]);
            acc[1] = fmaf(x0, wv.y, acc[1]);
            acc[2] = fmaf(x0, wv.z, acc[2]);
            acc[3] = fmaf(x0, wv.w, acc[3]);
        }
        if (more) {
            Xs[nxt][lkk][lr] = px0;
            #pragma unroll
            for (int p = 0; p < 4; p++) Ws[nxt][lkk][lr + p*16] = pw[p];
            __syncthreads();
        }
    }

    // epilogue: bias + activations
    const int h = h0 + tx;
    const int m = m0 + ty;
    float ig = sigm(acc[0] + bih[h]        + bhh[h]);
    float fg = sigm(acc[1] + bih[H_ + h]   + bhh[H_ + h]);
    float gg = tanhf(acc[2] + bih[2*H_ + h] + bhh[2*H_ + h]);
    float og = sigm(acc[3] + bih[3*H_ + h] + bhh[3*H_ + h]);
    float cn = fg * c_prev[m*H_ + h] + ig * gg;
    c_out[m*H_ + h] = cn;
    h_out[m*H_ + h] = og * tanhf(cn);
}

// ---------------------------------------------------------------------------
// Fused head GEMM: pre[m][n] = [sh1|c][m] . [W1|W2][n] + b1[n] + b2[n]
// Tile 16x64, K=256, grid (2,32)=64 blocks, 256 threads, double-buffered.
// ---------------------------------------------------------------------------
__global__ void __launch_bounds__(256) k_head(
    const float* __restrict__ sh1, const float* __restrict__ cvec,
    const float* __restrict__ W1, const float* __restrict__ W2,
    const float* __restrict__ b1, const float* __restrict__ b2)
{
    __shared__ float Xs[2][16][17];
    __shared__ float Ws[2][16][68];
    const int tid = threadIdx.x;
    const int tx = tid & 15, ty = tid >> 4;
    const int m0 = blockIdx.y * 16;
    const int n0 = blockIdx.x * 64;
    const int lkk = tid & 15, lr = tid >> 4;
    const int nt = 16;  // K=256

    {
        int k = lkk;
        Xs[0][lkk][lr] = sh1[(m0+lr)*H_ + k];
        #pragma unroll
        for (int p = 0; p < 4; p++)
            Ws[0][lkk][lr + p*16] = W1[(n0 + lr + p*16)*H_ + k];
    }
    __syncthreads();

    float acc[4] = {};
    for (int it = 0; it < nt; it++) {
        const int cur = it & 1, nxt = cur ^ 1;
        float px0 = 0.f, pw[4] = {0.f,0.f,0.f,0.f};
        const bool more = (it + 1 < nt);
        if (more) {
            int k = (it + 1) * 16 + lkk;
            if (k < H_) {
                px0 = sh1[(m0+lr)*H_ + k];
                #pragma unroll
                for (int p = 0; p < 4; p++) pw[p] = W1[(n0+lr+p*16)*H_ + k];
            } else {
                int k2 = k - H_;
                px0 = cvec[(m0+lr)*H_ + k2];
                #pragma unroll
                for (int p = 0; p < 4; p++) pw[p] = W2[(n0+lr+p*16)*H_ + k2];
            }
        }
        #pragma unroll
        for (int kk = 0; kk < 16; kk++) {
            float x0 = Xs[cur][kk][ty];
            float4 wv = *(const float4*)&Ws[cur][kk][tx*4];
            acc[0] = fmaf(x0, wv.x, acc[0]);
            acc[1] = fmaf(x0, wv.y, acc[1]);
            acc[2] = fmaf(x0, wv.z, acc[2]);
            acc[3] = fmaf(x0, wv.w, acc[3]);
        }
        if (more) {
            Xs[nxt][lkk][lr] = px0;
            #pragma unroll
            for (int p = 0; p < 4; p++) Ws[nxt][lkk][lr + p*16] = pw[p];
            __syncthreads();
        }
    }

    const int n = n0 + tx*4;
    const int m = m0 + ty;
    #pragma unroll
    for (int j = 0; j < 4; j++)
        g_pre[(size_t)m*H_ + n + j] = acc[j] + b1[n+j] + b2[n+j];
}

// ---------------------------------------------------------------------------
// Fused attention: scores + masked renormalized softmax + context, one block
// per batch row. 512 threads (16 warps). hk/hv each streamed exactly once.
// ---------------------------------------------------------------------------
__global__ void __launch_bounds__(512) k_attn(
    const float* __restrict__ hk, const float* __restrict__ hv,
    const float* __restrict__ q, const float* __restrict__ mask,
    float* __restrict__ c_out, float* __restrict__ att0)
{
    __shared__ float  sa[T_];          // scores -> attn (in place)
    __shared__ float4 sq[32];
    __shared__ float4 part[16][32];
    __shared__ float  red[512];
    const int b = blockIdx.x, tid = threadIdx.x;
    const int warp = tid >> 5, lane = tid & 31;

    if (tid < 32) sq[tid] = ((const float4*)(q + (size_t)b * H_))[tid];
    __syncthreads();
    const float4 qv = sq[lane];

    // Phase 1: scores. Warp w handles t in [w*128, (w+1)*128).
    const float4* kbase = (const float4*)(hk + (size_t)b * (T_ * H_));
    {
        const int tbeg = warp * 128;
        #pragma unroll 8
        for (int t = tbeg; t < tbeg + 128; t++) {
            float4 v = kbase[(size_t)t * 32 + lane];
            float d = v.x*qv.x + v.y*qv.y + v.z*qv.z + v.w*qv.w;
            d += __shfl_xor_sync(0xffffffffu, d, 16);
            d += __shfl_xor_sync(0xffffffffu, d, 8);
            d += __shfl_xor_sync(0xffffffffu, d, 4);
            d += __shfl_xor_sync(0xffffffffu, d, 2);
            d += __shfl_xor_sync(0xffffffffu, d, 1);
            if (lane == 0) sa[t] = d;
        }
    }
    __syncthreads();

    // Phase 2: masked, renormalized softmax (4 elems/thread)
    {
        const float* mk = mask + (size_t)b * T_;
        float loc[4];
        float mx = -1e30f;
        #pragma unroll
        for (int i = 0; i < 4; i++) { loc[i] = sa[tid + i*512]; mx = fmaxf(mx, loc[i]); }
        red[tid] = mx; __syncthreads();
        for (int st = 256; st > 0; st >>= 1) {
            if (tid < st) red[tid] = fmaxf(red[tid], red[tid + st]);
            __syncthreads();
        }
        mx = red[0]; __syncthreads();
        float sum = 0.f;
        #pragma unroll
        for (int i = 0; i < 4; i++) {
            float e = __expf(loc[i] - mx) * mk[tid + i*512];
            loc[i] = e; sum += e;
        }
        red[tid] = sum; __syncthreads();
        for (int st = 256; st > 0; st >>= 1) {
            if (tid < st) red[tid] += red[tid + st];
            __syncthreads();
        }
        const float inv = 1.f / red[0];
        #pragma unroll
        for (int i = 0; i < 4; i++) {
            float a = loc[i] * inv;
            sa[tid + i*512] = a;
            if (b == 0) att0[tid + i*512] = a;
        }
    }
    __syncthreads();

    // Phase 3: context. 16 warps split T (stride 16), lane owns 4 h (float4).
    // Two independent accumulators to break the FMA dependence chain.
    const float4* vbase = (const float4*)(hv + (size_t)b * (T_ * H_));
    float4 acc0 = make_float4(0.f, 0.f, 0.f, 0.f);
    float4 acc1 = make_float4(0.f, 0.f, 0.f, 0.f);
    #pragma unroll 4
    for (int t = warp; t < T_; t += 32) {
        float a = sa[t];
        float4 v = vbase[(size_t)t * 32 + lane];
        acc0.x = fmaf(a, v.x, acc0.x);
        acc0.y = fmaf(a, v.y, acc0.y);
        acc0.z = fmaf(a, v.z, acc0.z);
        acc0.w = fmaf(a, v.w, acc0.w);
        float a2 = sa[t + 16];
        float4 v2 = vbase[(size_t)(t + 16) * 32 + lane];
        acc1.x = fmaf(a2, v2.x, acc1.x);
        acc1.y = fmaf(a2, v2.y, acc1.y);
        acc1.z = fmaf(a2, v2.z, acc1.z);
        acc1.w = fmaf(a2, v2.w, acc1.w);
    }
    acc0.x += acc1.x; acc0.y += acc1.y; acc0.z += acc1.z; acc0.w += acc1.w;
    part[warp][lane] = acc0;
    __syncthreads();
    if (warp == 0) {
        float4 s = part[0][lane];
        #pragma unroll
        for (int w = 1; w < 16; w++) {
            float4 p = part[w][lane];
            s.x += p.x; s.y += p.y; s.z += p.z; s.w += p.w;
        }
        ((float4*)(c_out + (size_t)b * H_))[lane] = s;
    }
}

// ---------------------------------------------------------------------------
// BatchNorm training stats over batch (block per feature).
// ---------------------------------------------------------------------------
__global__ void k_bn(void) {
    int f = blockIdx.x, tid = threadIdx.x;
    float v0 = g_pre[(size_t)tid * H_ + f];
    float v1 = g_pre[(size_t)(tid + 256) * H_ + f];
    __shared__ float rs[256], rq[256];
    rs[tid] = v0 + v1;
    rq[tid] = v0 * v0 + v1 * v1;
    __syncthreads();
    for (int st = 128; st > 0; st >>= 1) {
        if (tid < st) { rs[tid] += rs[tid + st]; rq[tid] += rq[tid + st]; }
        __syncthreads();
    }
    if (tid == 0) {
        float mn = rs[0] * (1.f / 512.f);
        g_mean[f] = mn;
        g_var[f] = rq[0] * (1.f / 512.f) - mn * mn;
    }
}

// ---------------------------------------------------------------------------
// BN apply + ReLU + final linear (block per b, 128 thr = 4 warps,
// warp-per-output GEMV with shuffle reduce).
// ---------------------------------------------------------------------------
__global__ void k_final(const float* __restrict__ gamma, const float* __restrict__ beta,
                        const float* __restrict__ W3, const float* __restrict__ b3,
                        float* __restrict__ out) {
    int b = blockIdx.x, f = threadIdx.x;
    const int warp = f >> 5, lane = f & 31;
    __shared__ float sn[H_];
    float v = g_pre[(size_t)b * H_ + f];
    float n = (v - g_mean[f]) * rsqrtf(g_var[f] + 1e-5f) * gamma[f] + beta[f];
    sn[f] = fmaxf(n, 0.f);
    __syncthreads();
    float x0 = sn[lane], x1 = sn[lane + 32], x2 = sn[lane + 64], x3 = sn[lane + 96];
    for (int vo = warp; vo < V_; vo += 4) {
        const float* w = W3 + (size_t)vo * H_;
        float d = x0 * w[lane] + x1 * w[lane + 32] + x2 * w[lane + 64] + x3 * w[lane + 96];
        d += __shfl_xor_sync(0xffffffffu, d, 16);
        d += __shfl_xor_sync(0xffffffffu, d, 8);
        d += __shfl_xor_sync(0xffffffffu, d, 4);
        d += __shfl_xor_sync(0xffffffffu, d, 2);
        d += __shfl_xor_sync(0xffffffffu, d, 1);
        if (lane == 0) out[(size_t)b * V_ + vo] = d + b3[vo];
    }
}

// ---------------------------------------------------------------------------
extern "C" void kernel_launch(void* const* d_in, const int* in_sizes, int n_in,
                              void* d_out_v, int out_size) {
    const float* hk    = (const float*)d_in[0];
    const float* hv    = (const float*)d_in[1];
    const float* y_1   = (const float*)d_in[2];
    const float* c_1   = (const float*)d_in[3];
    const float* sh_1  = (const float*)d_in[4];   // [2,B,H]
    const float* sc_1  = (const float*)d_in[5];   // [2,B,H]
    const float* mask  = (const float*)d_in[6];
    const float* W_ih0 = (const float*)d_in[7];   // [512, 384]
    const float* W_hh0 = (const float*)d_in[8];   // [512, 128]
    const float* b_ih0 = (const float*)d_in[9];
    const float* b_hh0 = (const float*)d_in[10];
    const float* W_ih1 = (const float*)d_in[11];  // [512, 128]
    const float* W_hh1 = (const float*)d_in[12];  // [512, 128]
    const float* b_ih1 = (const float*)d_in[13];
    const float* b_hh1 = (const float*)d_in[14];
    const float* W1    = (const float*)d_in[15];  // [128, 128]
    const float* b1    = (const float*)d_in[16];
    const float* W2    = (const float*)d_in[17];  // [128, 128]
    const float* b2    = (const float*)d_in[18];
    const float* W3    = (const float*)d_in[19];  // [34, 128]
    const float* b3    = (const float*)d_in[20];
    const float* gamma = (const float*)d_in[21];
    const float* beta  = (const float*)d_in[22];
    float* d_out = (float*)d_out_v;
    (void)in_sizes; (void)n_in; (void)out_size;

    // LSTM cell 0: X = [y_1(256) | c_1(128) | sh_1[0](128)], Kin=384
    k_lstm<<<dim3(H_/16, B_/16), 256>>>(
        y_1, E_, c_1, H_, sh_1, H_,
        W_ih0, E_ + H_, W_hh0, b_ih0, b_hh0,
        sc_1, d_out + OFF_SH0, d_out + OFF_SC0);

    // LSTM cell 1: X = [sh0(128) | sh_1[1](128)], Kin=128
    k_lstm<<<dim3(H_/16, B_/16), 256>>>(
        d_out + OFF_SH0, H_, sh_1 + B_*H_, H_, (const float*)nullptr, 0,
        W_ih1, H_, W_hh1, b_ih1, b_hh1,
        sc_1 + B_*H_, d_out + OFF_SH1, d_out + OFF_SC1);

    // Attention (fused scores + softmax + context)
    k_attn<<<B_, 512>>>(hk, hv, d_out + OFF_SH1, mask,
                        d_out + OFF_C, d_out + OFF_ATT);

    // Head
    k_head<<<dim3(2, B_/16), 256>>>(d_out + OFF_SH1, d_out + OFF_C, W1, W2, b1, b2);
    k_bn<<<H_, 256>>>();
    k_final<<<B_, 128>>>(gamma, beta, W3, b3, d_out + OFF_OUT);
}